// round 6
// baseline (speedup 1.0000x reference)
#include <cuda_runtime.h>
#include <cuda_bf16.h>
#include <math.h>
#include <math_constants.h>

// Problem constants
#define BQ  8
#define HQ  8
#define BH  64          // B*H
#define LQ  2048
#define DQ  64
#define NSEL 40         // num selected queries == num sampled keys
#define SCALE 0.125f    // 64^-0.5
#define NEG_INF (-CUDART_INF_F)

// ---------------- scratch (device globals; no allocation allowed) ----------
__device__ float g_measure[BH * LQ];
__device__ int   g_topidx[BH * NSEL];
__device__ float g_rowMaxPart[BH * 8 * NSEL];
__device__ float g_rowSumPart[BH * 8 * NSEL];
__device__ float g_outSelPart[BH * 4 * NSEL * DQ];
__device__ float g_chunkSum[BH * 16 * DQ];

// ============================================================================
// K1: measure[bh][i] = max_j (q_i . k_{ridx[i,j]}) - (sum_j ...) / L
// Warp per query; 8 lanes per key (4 keys per load/shuffle step).
// launch_bounds(256,5) caps regs at 51 -> 5 CTAs/SM (occ 62.5% vs 44.9%).
// ============================================================================
__global__ __launch_bounds__(256, 5) void k_measure(const float* __restrict__ q,
                                                    const float* __restrict__ k,
                                                    const int* __restrict__ ridx) {
    const unsigned F = 0xffffffffu;
    int warp = (blockIdx.x * blockDim.x + threadIdx.x) >> 5;
    int lane = threadIdx.x & 31;
    int bh = warp >> 11;
    int i  = warp & 2047;
    int grp = lane >> 3;          // which key of the quad
    int p   = lane & 7;           // float4 slot within 32-dim half

    const float4* qrow = reinterpret_cast<const float4*>(q + ((size_t)bh * LQ + i) * DQ);
    float4 qv0 = qrow[p];         // dims [4p, 4p+4)
    float4 qv1 = qrow[8 + p];     // dims [32+4p, 32+4p+4)
    const float4* kb4 = reinterpret_cast<const float4*>(k + (size_t)bh * LQ * DQ);
    const int* rbase = ridx + i * NSEL + grp;

    float m = NEG_INF, s = 0.0f;
#pragma unroll
    for (int h = 0; h < NSEL / 4; h += 2) {
        int ra = rbase[4 * h];            // key 4h+grp
        int rb = rbase[4 * h + 4];        // key 4(h+1)+grp
        const float4* kra = kb4 + (size_t)ra * (DQ / 4);
        const float4* krb = kb4 + (size_t)rb * (DQ / 4);
        float4 a0 = kra[p];
        float4 a1 = kra[8 + p];
        float4 b0 = krb[p];
        float4 b1 = krb[8 + p];
        float da = qv0.x * a0.x + qv0.y * a0.y + qv0.z * a0.z + qv0.w * a0.w;
        da += qv1.x * a1.x + qv1.y * a1.y + qv1.z * a1.z + qv1.w * a1.w;
        float db = qv0.x * b0.x + qv0.y * b0.y + qv0.z * b0.z + qv0.w * b0.w;
        db += qv1.x * b1.x + qv1.y * b1.y + qv1.z * b1.z + qv1.w * b1.w;
        da += __shfl_xor_sync(F, da, 1);
        db += __shfl_xor_sync(F, db, 1);
        da += __shfl_xor_sync(F, da, 2);
        db += __shfl_xor_sync(F, db, 2);
        da += __shfl_xor_sync(F, da, 4);
        db += __shfl_xor_sync(F, db, 4);
        m = fmaxf(m, fmaxf(da, db));
        s += da + db;
    }
    m = fmaxf(m, __shfl_xor_sync(F, m, 8));
    s += __shfl_xor_sync(F, s, 8);
    m = fmaxf(m, __shfl_xor_sync(F, m, 16));
    s += __shfl_xor_sync(F, s, 16);
    if (lane == 0) g_measure[bh * LQ + i] = m - s * (1.0f / (float)LQ);
}

// ============================================================================
// K2: per (b,h) top-40 of 2048 via 4-pass byte radix select + rank sort.
// Matches jax.lax.top_k: descending value, ties -> lower index first.
// ============================================================================
__global__ void k_topk() {
    __shared__ unsigned ukey[LQ];
    __shared__ int hist[256];
    __shared__ int ssum[256];
    __shared__ int wsum[8];
    __shared__ int s_chosen;
    __shared__ int s_target;
    __shared__ int cnt_gt;
    __shared__ unsigned selKey[64];
    __shared__ int selIdx[64];
    __shared__ int tcnt[256];

    int bh = blockIdx.x, t = threadIdx.x, lane = t & 31, w = t >> 5;

    for (int e = t; e < LQ; e += 256) {
        unsigned b = __float_as_uint(g_measure[bh * LQ + e]);
        ukey[e] = (b & 0x80000000u) ? ~b : (b | 0x80000000u);
    }
    if (t == 0) { s_target = NSEL; cnt_gt = 0; }
    __syncthreads();

    unsigned prefix = 0;
    for (int pass = 3; pass >= 0; pass--) {
        int shift = pass * 8;
        hist[t] = 0;
        __syncthreads();
        unsigned himask = (pass == 3) ? 0u : (0xFFFFFFFFu << (shift + 8));
        for (int e = t; e < LQ; e += 256) {
            unsigned u = ukey[e];
            if ((u & himask) == (prefix & himask))
                atomicAdd(&hist[(u >> shift) & 255], 1);
        }
        __syncthreads();
        int r = 255 - t;
        int x = hist[r];
#pragma unroll
        for (int o = 1; o < 32; o <<= 1) {
            int y = __shfl_up_sync(0xffffffffu, x, o);
            if (lane >= o) x += y;
        }
        if (lane == 31) wsum[w] = x;
        __syncthreads();
        if (w == 0 && lane < 8) {
            int y = wsum[lane];
#pragma unroll
            for (int o = 1; o < 8; o <<= 1) {
                int z = __shfl_up_sync(0xffu, y, o);
                if (lane >= o) y += z;
            }
            wsum[lane] = y;
        }
        __syncthreads();
        int S = x + (w > 0 ? wsum[w - 1] : 0);
        ssum[r] = S;
        __syncthreads();
        int target = s_target;
        int Sb = ssum[t];
        int Sb1 = (t == 255) ? 0 : ssum[t + 1];
        if (Sb >= target && Sb1 < target) s_chosen = t;
        __syncthreads();
        int chosen = s_chosen;
        prefix |= ((unsigned)chosen) << shift;
        if (t == 0) s_target = target - ((chosen == 255) ? 0 : ssum[chosen + 1]);
        __syncthreads();
    }
    unsigned T = prefix;
    int need_eq = s_target;
    int count_gt = NSEL - need_eq;

    int mytie = 0;
#pragma unroll
    for (int e2 = 0; e2 < 8; e2++) {
        int e = t * 8 + e2;
        unsigned u = ukey[e];
        if (u > T) {
            int p = atomicAdd(&cnt_gt, 1);
            selKey[p] = u; selIdx[p] = e;
        } else if (u == T) mytie++;
    }
    tcnt[t] = mytie;
    __syncthreads();
    {
        int x = tcnt[t];
#pragma unroll
        for (int o = 1; o < 32; o <<= 1) {
            int y = __shfl_up_sync(0xffffffffu, x, o);
            if (lane >= o) x += y;
        }
        if (lane == 31) wsum[w] = x;
        __syncthreads();
        if (w == 0 && lane < 8) {
            int y = wsum[lane];
#pragma unroll
            for (int o = 1; o < 8; o <<= 1) {
                int z = __shfl_up_sync(0xffu, y, o);
                if (lane >= o) y += z;
            }
            wsum[lane] = y;
        }
        __syncthreads();
        int run = x - tcnt[t] + (w > 0 ? wsum[w - 1] : 0);
#pragma unroll
        for (int e2 = 0; e2 < 8; e2++) {
            int e = t * 8 + e2;
            if (ukey[e] == T) {
                if (run < need_eq) { selKey[count_gt + run] = T; selIdx[count_gt + run] = e; }
                run++;
            }
        }
    }
    __syncthreads();
    if (t < NSEL) {
        unsigned mk = selKey[t]; int mi = selIdx[t];
        int rank = 0;
        for (int f = 0; f < NSEL; f++) {
            unsigned fk = selKey[f]; int fi = selIdx[f];
            if (fk > mk || (fk == mk && fi < mi)) rank++;
        }
        g_topidx[bh * NSEL + rank] = mi;
    }
}

// ============================================================================
// K3: logits = (q_sel @ k^T)*SCALE + causal mask -> attn AND smem copy;
// per-row partial max/sumexp computed from the SMEM copy (no global re-read).
// grid (BH, 8), block 256, dynamic smem.
// ============================================================================
#define SMEM_LOGITS ((NSEL * DQ + 128 * 65 + NSEL * 256) * 4)

__global__ void k_logits(const float* __restrict__ q,
                         const float* __restrict__ k,
                         float* __restrict__ attn) {
    extern __shared__ float dynL[];
    float* qs = dynL;                          // 40*64
    float* ks = dynL + NSEL * DQ;              // 128*65 (padded)
    float* ls = ks + 128 * 65;                 // 40*256 logits copy
    __shared__ int sidx[NSEL];

    int bh = blockIdx.x, js = blockIdx.y, t = threadIdx.x;
    if (t < NSEL) sidx[t] = g_topidx[bh * NSEL + t];
    __syncthreads();

    for (int e = t; e < NSEL * DQ; e += 256) {
        int s = e >> 6, d = e & 63;
        qs[e] = q[((size_t)bh * LQ + sidx[s]) * DQ + d];
    }

    float* attnBH = attn + (size_t)bh * NSEL * LQ;
    int tx = t & 63, ty = t >> 6;   // tx: key col base, ty: 0..3 row group

    for (int sub = 0; sub < 2; sub++) {
        int j0 = js * 256 + sub * 128;
        __syncthreads();
        for (int e = t; e < 128 * DQ; e += 256) {
            int r = e >> 6, d = e & 63;
            ks[r * 65 + d] = k[((size_t)bh * LQ + j0 + r) * DQ + d];
        }
        __syncthreads();

        float acc[10][2];
#pragma unroll
        for (int r = 0; r < 10; r++) { acc[r][0] = 0.0f; acc[r][1] = 0.0f; }

#pragma unroll 4
        for (int d = 0; d < DQ; d++) {
            float k0 = ks[tx * 65 + d];
            float k1 = ks[(tx + 64) * 65 + d];
#pragma unroll
            for (int r = 0; r < 10; r++) {
                float qv = qs[(ty + 4 * r) * DQ + d];
                acc[r][0] = fmaf(qv, k0, acc[r][0]);
                acc[r][1] = fmaf(qv, k1, acc[r][1]);
            }
        }
#pragma unroll
        for (int r = 0; r < 10; r++) {
            int s = ty + 4 * r;
            int lim = sidx[s];
            int jl0 = sub * 128 + tx;
            int jl1 = sub * 128 + tx + 64;
            int jg0 = js * 256 + jl0;
            int jg1 = js * 256 + jl1;
            float v0 = (jg0 > lim) ? NEG_INF : acc[r][0] * SCALE;
            float v1 = (jg1 > lim) ? NEG_INF : acc[r][1] * SCALE;
            attnBH[(size_t)s * LQ + jg0] = v0;
            attnBH[(size_t)s * LQ + jg1] = v1;
            ls[s * 256 + jl0] = v0;
            ls[s * 256 + jl1] = v1;
        }
    }
    __syncthreads();

    // partial softmax stats over this block's 256-key span (from smem)
    int w = t >> 5, lane = t & 31;
    for (int rr = 0; rr < 5; rr++) {
        int s = w + 8 * rr;
        const float* base = ls + s * 256;
        float m = NEG_INF;
#pragma unroll
        for (int u = 0; u < 8; u++) m = fmaxf(m, base[lane + 32 * u]);
        m = fmaxf(m, __shfl_xor_sync(0xffffffffu, m, 16));
        m = fmaxf(m, __shfl_xor_sync(0xffffffffu, m, 8));
        m = fmaxf(m, __shfl_xor_sync(0xffffffffu, m, 4));
        m = fmaxf(m, __shfl_xor_sync(0xffffffffu, m, 2));
        m = fmaxf(m, __shfl_xor_sync(0xffffffffu, m, 1));
        float ssum = 0.0f;
        if (m > NEG_INF) {
#pragma unroll
            for (int u = 0; u < 8; u++) ssum += expf(base[lane + 32 * u] - m);
        }
        ssum += __shfl_xor_sync(0xffffffffu, ssum, 16);
        ssum += __shfl_xor_sync(0xffffffffu, ssum, 8);
        ssum += __shfl_xor_sync(0xffffffffu, ssum, 4);
        ssum += __shfl_xor_sync(0xffffffffu, ssum, 2);
        ssum += __shfl_xor_sync(0xffffffffu, ssum, 1);
        if (lane == 0) {
            g_rowMaxPart[(bh * 8 + js) * NSEL + s] = m;
            g_rowSumPart[(bh * 8 + js) * NSEL + s] = ssum;
        }
    }
}

// ============================================================================
// cumsum(v, axis=L): 3-pass chunk scan (chunk = 128 rows, 16 chunks)
// ============================================================================
__global__ void k_csumA(const float* __restrict__ v) {       // grid (BH,16), 256 thr
    int bh = blockIdx.x, c = blockIdx.y, t = threadIdx.x;
    int d = t & 63, g = t >> 6;
    const float* base = v + ((size_t)bh * LQ + c * 128) * DQ;
    float s = 0.0f;
#pragma unroll 8
    for (int r = g * 32; r < g * 32 + 32; r++) s += base[(size_t)r * DQ + d];
    __shared__ float red[256];
    red[t] = s;
    __syncthreads();
    if (g == 0)
        g_chunkSum[(bh * 16 + c) * DQ + d] = red[d] + red[64 + d] + red[128 + d] + red[192 + d];
}

__global__ void k_csumB() {                                  // grid BH, 64 thr
    int bh = blockIdx.x, d = threadIdx.x;
    float run = 0.0f;
#pragma unroll
    for (int c = 0; c < 16; c++) {
        float x = g_chunkSum[(bh * 16 + c) * DQ + d];
        g_chunkSum[(bh * 16 + c) * DQ + d] = run;   // exclusive
        run += x;
    }
}

__global__ void k_csumC(const float* __restrict__ v, float* __restrict__ out) { // grid (BH,16), 64 thr
    int bh = blockIdx.x, c = blockIdx.y, d = threadIdx.x;
    const float* base = v + ((size_t)bh * LQ + c * 128) * DQ;
    float* obase = out + ((size_t)bh * LQ + c * 128) * DQ;
    float run = g_chunkSum[(bh * 16 + c) * DQ + d];
#pragma unroll 8
    for (int r = 0; r < 128; r++) {
        run += base[(size_t)r * DQ + d];
        obase[(size_t)r * DQ + d] = run;
    }
}

// ============================================================================
// K4: rowMax/rowInv computed in-block from partials; probs -> attn in place;
// P@V partial per (bh, js) written WITHOUT atomics to g_outSelPart.
// grid (BH, 4 jsplits of 512 keys), block 256.
// ============================================================================
__global__ void k_pv(const float* __restrict__ v, float* __restrict__ attn) {
    __shared__ float vs[64 * DQ];     // 16 KB
    __shared__ float ps[NSEL * 64];   // 10 KB (reused at end as [s][d] merge)
    __shared__ float sMax[NSEL], sInv[NSEL];

    int bh = blockIdx.x, js = blockIdx.y, t = threadIdx.x;
    if (t < NSEL) {
        float fm = NEG_INF;
#pragma unroll
        for (int p = 0; p < 8; p++)
            fm = fmaxf(fm, g_rowMaxPart[(bh * 8 + p) * NSEL + t]);
        float fs = 0.0f;
#pragma unroll
        for (int p = 0; p < 8; p++) {
            float pm = g_rowMaxPart[(bh * 8 + p) * NSEL + t];
            float pssum = g_rowSumPart[(bh * 8 + p) * NSEL + t];
            fs += pssum * expf(pm - fm);   // pm=-inf -> pssum==0 -> contributes 0
        }
        sMax[t] = fm;
        sInv[t] = 1.0f / fs;
    }

    float* attnBH = attn + (size_t)bh * NSEL * LQ;
    const float* vBH = v + (size_t)bh * LQ * DQ;

    int tx = t & 31, ty = t >> 5;
    int g = ty >> 2;       // key half: 0 or 1 (32 keys each)
    int sy = ty & 3;       // row group: s = sy + 4r

    float acc[10][2];
#pragma unroll
    for (int r = 0; r < 10; r++) { acc[r][0] = 0.0f; acc[r][1] = 0.0f; }
    __syncthreads();

    for (int tile = 0; tile < 8; tile++) {
        int j0 = js * 512 + tile * 64;
        __syncthreads();
        const float4* vsrc = reinterpret_cast<const float4*>(vBH + (size_t)j0 * DQ);
        float4* vdst = reinterpret_cast<float4*>(vs);
        for (int e = t; e < 64 * DQ / 4; e += 256) vdst[e] = vsrc[e];
        for (int e = t; e < NSEL * 64; e += 256) {
            int s = e >> 6, jj = e & 63;
            size_t a = (size_t)s * LQ + j0 + jj;
            float l = attnBH[a];
            float p = expf(l - sMax[s]) * sInv[s];
            attnBH[a] = p;
            ps[e] = p;
        }
        __syncthreads();
#pragma unroll 4
        for (int jl = g * 32; jl < g * 32 + 32; jl++) {
            float2 vv = *reinterpret_cast<const float2*>(&vs[jl * DQ + 2 * tx]);
#pragma unroll
            for (int r = 0; r < 10; r++) {
                float p = ps[(sy + 4 * r) * 64 + jl];
                acc[r][0] = fmaf(p, vv.x, acc[r][0]);
                acc[r][1] = fmaf(p, vv.y, acc[r][1]);
            }
        }
    }
    // merge the two key-half groups in smem (ps reused as [s][d]), then store
    __syncthreads();
    if (g == 0) {
#pragma unroll
        for (int r = 0; r < 10; r++) {
            int s = sy + 4 * r;
            ps[s * DQ + 2 * tx]     = acc[r][0];
            ps[s * DQ + 2 * tx + 1] = acc[r][1];
        }
    }
    __syncthreads();
    if (g == 1) {
#pragma unroll
        for (int r = 0; r < 10; r++) {
            int s = sy + 4 * r;
            ps[s * DQ + 2 * tx]     += acc[r][0];
            ps[s * DQ + 2 * tx + 1] += acc[r][1];
        }
    }
    __syncthreads();
    float* part = g_outSelPart + ((size_t)(bh * 4 + js)) * NSEL * DQ;
    for (int e = t; e < NSEL * DQ; e += 256) part[e] = ps[e];
}

// ============================================================================
// K6: sum the 4 P@V partials, scatter into out at the selected positions
// ============================================================================
__global__ void k_scatter(float* __restrict__ out) {   // grid BH, 256 thr
    int bh = blockIdx.x, t = threadIdx.x;
    const float* p0 = g_outSelPart + ((size_t)(bh * 4 + 0)) * NSEL * DQ;
    const float* p1 = g_outSelPart + ((size_t)(bh * 4 + 1)) * NSEL * DQ;
    const float* p2 = g_outSelPart + ((size_t)(bh * 4 + 2)) * NSEL * DQ;
    const float* p3 = g_outSelPart + ((size_t)(bh * 4 + 3)) * NSEL * DQ;
    for (int e = t; e < NSEL * DQ; e += 256) {
        int s = e >> 6, d = e & 63;
        out[((size_t)bh * LQ + g_topidx[bh * NSEL + s]) * DQ + d] =
            p0[e] + p1[e] + p2[e] + p3[e];
    }
}

// ============================================================================
extern "C" void kernel_launch(void* const* d_in, const int* in_sizes, int n_in,
                              void* d_out, int out_size) {
    const float* q = (const float*)d_in[0];
    const float* k = (const float*)d_in[1];
    const float* v = (const float*)d_in[2];
    const int* ridx = (const int*)d_in[3];

    float* out  = (float*)d_out;                        // [BH, L, D]
    float* attn = out + (size_t)BH * LQ * DQ;           // [BH, NSEL, L]

    cudaFuncSetAttribute(k_logits, cudaFuncAttributeMaxDynamicSharedMemorySize, SMEM_LOGITS);

    // cumsum chain first (depends only on v); keeps measure in ncu window.
    {
        dim3 grid(BH, 16);
        k_csumA<<<grid, 256>>>(v);
        k_csumB<<<BH, 64>>>();
        k_csumC<<<grid, 64>>>(v, out);
    }
    // 1. measure (warp-per-query, 8-lane-per-key gather)
    k_measure<<<(BH * LQ) / 8, 256>>>(q, k, ridx);
    // 2. top-k selection (radix select)
    k_topk<<<BH, 256>>>();
    // 3. logits + partial softmax stats (smem-resident stats)
    {
        dim3 grid(BH, 8);
        k_logits<<<grid, 256, SMEM_LOGITS>>>(q, k, attn);
    }
    // 4. softmax probs (in place) + P@V partials (no atomics, no combine kernel)
    {
        dim3 grid(BH, 4);
        k_pv<<<grid, 256>>>(v, attn);
    }
    // 5. sum partials + scatter selected rows into out
    k_scatter<<<BH, 256>>>(out);
}

// round 7
// speedup vs baseline: 1.0292x; 1.0292x over previous
#include <cuda_runtime.h>
#include <cuda_bf16.h>
#include <math.h>
#include <math_constants.h>

// Problem constants
#define BQ  8
#define HQ  8
#define BH  64          // B*H
#define LQ  2048
#define DQ  64
#define NSEL 40         // num selected queries == num sampled keys
#define SCALE 0.125f    // 64^-0.5
#define NEG_INF (-CUDART_INF_F)

// cumsum chunking: 64 chunks of 32 rows
#define NCHUNK 64
#define CHROWS 32

// ---------------- scratch (device globals; no allocation allowed) ----------
__device__ float g_measure[BH * LQ];
__device__ int   g_topidx[BH * NSEL];
__device__ float g_rowMaxPart[BH * 8 * NSEL];
__device__ float g_rowSumPart[BH * 8 * NSEL];
__device__ float g_outSelPart[BH * 4 * NSEL * DQ];
__device__ float g_chunkSum[BH * NCHUNK * DQ];

// ============================================================================
// K1: fused  [csumA: 1024 blocks]  +  [measure: 16384 blocks]
// csumA blocks come first so they schedule early and finish well before the
// end of the (much larger) measure wave.
// measure: warp per query; 8 lanes per key (R5 body, no launch_bounds cap).
// ============================================================================
__global__ __launch_bounds__(256) void k_meas_csumA(const float* __restrict__ q,
                                                    const float* __restrict__ k,
                                                    const int* __restrict__ ridx,
                                                    const float* __restrict__ v) {
    int bid = blockIdx.x;
    if (bid < 1024) {
        // ---- csumA: per-chunk sums. block = (bh, 4 chunks), thread=(sub,d)
        int bh = bid >> 4, cg = bid & 15;
        int t = threadIdx.x;
        int d = t & 63, sub = t >> 6;
        int c = cg * 4 + sub;
        const float* base = v + ((size_t)bh * LQ + c * CHROWS) * DQ;
        float s = 0.0f;
#pragma unroll 8
        for (int r = 0; r < CHROWS; r++) s += base[(size_t)r * DQ + d];
        g_chunkSum[((size_t)bh * NCHUNK + c) * DQ + d] = s;
        return;
    }
    // ---- measure
    const unsigned F = 0xffffffffu;
    int warp = ((bid - 1024) * 256 + (int)threadIdx.x) >> 5;
    int lane = threadIdx.x & 31;
    int bh = warp >> 11;
    int i  = warp & 2047;
    int grp = lane >> 3;          // which key of the quad
    int p   = lane & 7;           // float4 slot within 32-dim half

    const float4* qrow = reinterpret_cast<const float4*>(q + ((size_t)bh * LQ + i) * DQ);
    float4 qv0 = qrow[p];         // dims [4p, 4p+4)
    float4 qv1 = qrow[8 + p];     // dims [32+4p, 32+4p+4)
    const float4* kb4 = reinterpret_cast<const float4*>(k + (size_t)bh * LQ * DQ);
    const int* rbase = ridx + i * NSEL + grp;

    float m = NEG_INF, s = 0.0f;
#pragma unroll
    for (int h = 0; h < NSEL / 4; h += 2) {
        int ra = rbase[4 * h];            // key 4h+grp
        int rb = rbase[4 * h + 4];        // key 4(h+1)+grp
        const float4* kra = kb4 + (size_t)ra * (DQ / 4);
        const float4* krb = kb4 + (size_t)rb * (DQ / 4);
        float4 a0 = kra[p];
        float4 a1 = kra[8 + p];
        float4 b0 = krb[p];
        float4 b1 = krb[8 + p];
        float da = qv0.x * a0.x + qv0.y * a0.y + qv0.z * a0.z + qv0.w * a0.w;
        da += qv1.x * a1.x + qv1.y * a1.y + qv1.z * a1.z + qv1.w * a1.w;
        float db = qv0.x * b0.x + qv0.y * b0.y + qv0.z * b0.z + qv0.w * b0.w;
        db += qv1.x * b1.x + qv1.y * b1.y + qv1.z * b1.z + qv1.w * b1.w;
        da += __shfl_xor_sync(F, da, 1);
        db += __shfl_xor_sync(F, db, 1);
        da += __shfl_xor_sync(F, da, 2);
        db += __shfl_xor_sync(F, db, 2);
        da += __shfl_xor_sync(F, da, 4);
        db += __shfl_xor_sync(F, db, 4);
        m = fmaxf(m, fmaxf(da, db));
        s += da + db;
    }
    m = fmaxf(m, __shfl_xor_sync(F, m, 8));
    s += __shfl_xor_sync(F, s, 8);
    m = fmaxf(m, __shfl_xor_sync(F, m, 16));
    s += __shfl_xor_sync(F, s, 16);
    if (lane == 0) g_measure[bh * LQ + i] = m - s * (1.0f / (float)LQ);
}

// ============================================================================
// K2: fused  [topk: 64 blocks]  +  [csumB: 64 blocks]
// topk: 4-pass byte radix select + rank sort (jax.lax.top_k order).
// csumB: serial exclusive scan of 64 chunk sums per (bh, d).
// ============================================================================
__global__ __launch_bounds__(256) void k_topk_csumB() {
    int bid = blockIdx.x;
    if (bid >= BH) {
        // ---- csumB
        int bh = bid - BH;
        int d = threadIdx.x;
        if (d < DQ) {
            float run = 0.0f;
#pragma unroll
            for (int c = 0; c < NCHUNK; c++) {
                size_t a = ((size_t)bh * NCHUNK + c) * DQ + d;
                float x = g_chunkSum[a];
                g_chunkSum[a] = run;   // exclusive
                run += x;
            }
        }
        return;
    }
    // ---- topk
    __shared__ unsigned ukey[LQ];
    __shared__ int hist[256];
    __shared__ int ssum[256];
    __shared__ int wsum[8];
    __shared__ int s_chosen;
    __shared__ int s_target;
    __shared__ int cnt_gt;
    __shared__ unsigned selKey[64];
    __shared__ int selIdx[64];
    __shared__ int tcnt[256];

    int bh = bid, t = threadIdx.x, lane = t & 31, w = t >> 5;

    for (int e = t; e < LQ; e += 256) {
        unsigned b = __float_as_uint(g_measure[bh * LQ + e]);
        ukey[e] = (b & 0x80000000u) ? ~b : (b | 0x80000000u);
    }
    if (t == 0) { s_target = NSEL; cnt_gt = 0; }
    __syncthreads();

    unsigned prefix = 0;
    for (int pass = 3; pass >= 0; pass--) {
        int shift = pass * 8;
        hist[t] = 0;
        __syncthreads();
        unsigned himask = (pass == 3) ? 0u : (0xFFFFFFFFu << (shift + 8));
        for (int e = t; e < LQ; e += 256) {
            unsigned u = ukey[e];
            if ((u & himask) == (prefix & himask))
                atomicAdd(&hist[(u >> shift) & 255], 1);
        }
        __syncthreads();
        int r = 255 - t;
        int x = hist[r];
#pragma unroll
        for (int o = 1; o < 32; o <<= 1) {
            int y = __shfl_up_sync(0xffffffffu, x, o);
            if (lane >= o) x += y;
        }
        if (lane == 31) wsum[w] = x;
        __syncthreads();
        if (w == 0 && lane < 8) {
            int y = wsum[lane];
#pragma unroll
            for (int o = 1; o < 8; o <<= 1) {
                int z = __shfl_up_sync(0xffu, y, o);
                if (lane >= o) y += z;
            }
            wsum[lane] = y;
        }
        __syncthreads();
        int S = x + (w > 0 ? wsum[w - 1] : 0);
        ssum[r] = S;
        __syncthreads();
        int target = s_target;
        int Sb = ssum[t];
        int Sb1 = (t == 255) ? 0 : ssum[t + 1];
        if (Sb >= target && Sb1 < target) s_chosen = t;
        __syncthreads();
        int chosen = s_chosen;
        prefix |= ((unsigned)chosen) << shift;
        if (t == 0) s_target = target - ((chosen == 255) ? 0 : ssum[chosen + 1]);
        __syncthreads();
    }
    unsigned T = prefix;
    int need_eq = s_target;
    int count_gt = NSEL - need_eq;

    int mytie = 0;
#pragma unroll
    for (int e2 = 0; e2 < 8; e2++) {
        int e = t * 8 + e2;
        unsigned u = ukey[e];
        if (u > T) {
            int p = atomicAdd(&cnt_gt, 1);
            selKey[p] = u; selIdx[p] = e;
        } else if (u == T) mytie++;
    }
    tcnt[t] = mytie;
    __syncthreads();
    {
        int x = tcnt[t];
#pragma unroll
        for (int o = 1; o < 32; o <<= 1) {
            int y = __shfl_up_sync(0xffffffffu, x, o);
            if (lane >= o) x += y;
        }
        if (lane == 31) wsum[w] = x;
        __syncthreads();
        if (w == 0 && lane < 8) {
            int y = wsum[lane];
#pragma unroll
            for (int o = 1; o < 8; o <<= 1) {
                int z = __shfl_up_sync(0xffu, y, o);
                if (lane >= o) y += z;
            }
            wsum[lane] = y;
        }
        __syncthreads();
        int run = x - tcnt[t] + (w > 0 ? wsum[w - 1] : 0);
#pragma unroll
        for (int e2 = 0; e2 < 8; e2++) {
            int e = t * 8 + e2;
            if (ukey[e] == T) {
                if (run < need_eq) { selKey[count_gt + run] = T; selIdx[count_gt + run] = e; }
                run++;
            }
        }
    }
    __syncthreads();
    if (t < NSEL) {
        unsigned mk = selKey[t]; int mi = selIdx[t];
        int rank = 0;
        for (int f = 0; f < NSEL; f++) {
            unsigned fk = selKey[f]; int fi = selIdx[f];
            if (fk > mk || (fk == mk && fi < mi)) rank++;
        }
        g_topidx[bh * NSEL + rank] = mi;
    }
}

// ============================================================================
// K3: fused  [csumC: 1024 blocks]  +  [logits: 512 blocks]
// csumC: final cumsum pass, 32 serial rows per thread.
// logits (R5 body): q_sel @ k^T * SCALE + causal mask -> attn; partial
// max/sumexp per 256-key split (re-read from global; that version benched best).
// ============================================================================
__global__ __launch_bounds__(256) void k_logits_csumC(const float* __restrict__ q,
                                                      const float* __restrict__ k,
                                                      const float* __restrict__ v,
                                                      float* __restrict__ out,
                                                      float* __restrict__ attn) {
    __shared__ float qs[NSEL * DQ];        // 40x64
    __shared__ float ks[128 * 65];         // padded
    __shared__ int   sidx[NSEL];

    int bid = blockIdx.x;
    if (bid < 1024) {
        // ---- csumC
        int bh = bid >> 4, cg = bid & 15;
        int t = threadIdx.x;
        int d = t & 63, sub = t >> 6;
        int c = cg * 4 + sub;
        const float* base = v + ((size_t)bh * LQ + c * CHROWS) * DQ;
        float* obase = out + ((size_t)bh * LQ + c * CHROWS) * DQ;
        float run = g_chunkSum[((size_t)bh * NCHUNK + c) * DQ + d];
#pragma unroll 8
        for (int r = 0; r < CHROWS; r++) {
            run += base[(size_t)r * DQ + d];
            obase[(size_t)r * DQ + d] = run;
        }
        return;
    }
    // ---- logits
    int lb = bid - 1024;
    int bh = lb >> 3, js = lb & 7, t = threadIdx.x;
    if (t < NSEL) sidx[t] = g_topidx[bh * NSEL + t];
    __syncthreads();

    for (int e = t; e < NSEL * DQ; e += 256) {
        int s = e >> 6, d = e & 63;
        qs[e] = q[((size_t)bh * LQ + sidx[s]) * DQ + d];
    }

    float* attnBH = attn + (size_t)bh * NSEL * LQ;
    int tx = t & 63, ty = t >> 6;   // tx: key col base, ty: 0..3 row group

    for (int sub = 0; sub < 2; sub++) {
        int j0 = js * 256 + sub * 128;
        __syncthreads();
        for (int e = t; e < 128 * DQ; e += 256) {
            int r = e >> 6, d = e & 63;
            ks[r * 65 + d] = k[((size_t)bh * LQ + j0 + r) * DQ + d];
        }
        __syncthreads();

        float acc[10][2];
#pragma unroll
        for (int r = 0; r < 10; r++) { acc[r][0] = 0.0f; acc[r][1] = 0.0f; }

#pragma unroll 4
        for (int d = 0; d < DQ; d++) {
            float k0 = ks[tx * 65 + d];
            float k1 = ks[(tx + 64) * 65 + d];
#pragma unroll
            for (int r = 0; r < 10; r++) {
                float qv = qs[(ty + 4 * r) * DQ + d];
                acc[r][0] = fmaf(qv, k0, acc[r][0]);
                acc[r][1] = fmaf(qv, k1, acc[r][1]);
            }
        }
#pragma unroll
        for (int r = 0; r < 10; r++) {
            int s = ty + 4 * r;
            int lim = sidx[s];
            int jg0 = j0 + tx;
            int jg1 = j0 + tx + 64;
            attnBH[(size_t)s * LQ + jg0] = (jg0 > lim) ? NEG_INF : acc[r][0] * SCALE;
            attnBH[(size_t)s * LQ + jg1] = (jg1 > lim) ? NEG_INF : acc[r][1] * SCALE;
        }
    }
    __syncthreads();   // make our global logit writes visible block-wide

    // partial softmax stats over this block's 256-key span
    int w = t >> 5, lane = t & 31;
    for (int rr = 0; rr < 5; rr++) {
        int s = w + 8 * rr;
        size_t base = (size_t)s * LQ + js * 256;
        float m = NEG_INF;
#pragma unroll
        for (int u = 0; u < 8; u++) m = fmaxf(m, attnBH[base + lane + 32 * u]);
        m = fmaxf(m, __shfl_xor_sync(0xffffffffu, m, 16));
        m = fmaxf(m, __shfl_xor_sync(0xffffffffu, m, 8));
        m = fmaxf(m, __shfl_xor_sync(0xffffffffu, m, 4));
        m = fmaxf(m, __shfl_xor_sync(0xffffffffu, m, 2));
        m = fmaxf(m, __shfl_xor_sync(0xffffffffu, m, 1));
        float ssum = 0.0f;
        if (m > NEG_INF) {
#pragma unroll
            for (int u = 0; u < 8; u++) ssum += expf(attnBH[base + lane + 32 * u] - m);
        }
        ssum += __shfl_xor_sync(0xffffffffu, ssum, 16);
        ssum += __shfl_xor_sync(0xffffffffu, ssum, 8);
        ssum += __shfl_xor_sync(0xffffffffu, ssum, 4);
        ssum += __shfl_xor_sync(0xffffffffu, ssum, 2);
        ssum += __shfl_xor_sync(0xffffffffu, ssum, 1);
        if (lane == 0) {
            g_rowMaxPart[(bh * 8 + js) * NSEL + s] = m;
            g_rowSumPart[(bh * 8 + js) * NSEL + s] = ssum;
        }
    }
}

// ============================================================================
// K4: rowMax/rowInv from partials in-block; probs -> attn in place;
// P@V partial per (bh, js) written WITHOUT atomics to g_outSelPart.
// grid (BH, 4), block 256.
// ============================================================================
__global__ void k_pv(const float* __restrict__ v, float* __restrict__ attn) {
    __shared__ float vs[64 * DQ];     // 16 KB
    __shared__ float ps[NSEL * 64];   // 10 KB (reused at end as [s][d] merge)
    __shared__ float sMax[NSEL], sInv[NSEL];

    int bh = blockIdx.x, js = blockIdx.y, t = threadIdx.x;
    if (t < NSEL) {
        float fm = NEG_INF;
#pragma unroll
        for (int p = 0; p < 8; p++)
            fm = fmaxf(fm, g_rowMaxPart[(bh * 8 + p) * NSEL + t]);
        float fs = 0.0f;
#pragma unroll
        for (int p = 0; p < 8; p++) {
            float pm = g_rowMaxPart[(bh * 8 + p) * NSEL + t];
            float pssum = g_rowSumPart[(bh * 8 + p) * NSEL + t];
            fs += pssum * expf(pm - fm);   // pm=-inf -> pssum==0 -> contributes 0
        }
        sMax[t] = fm;
        sInv[t] = 1.0f / fs;
    }

    float* attnBH = attn + (size_t)bh * NSEL * LQ;
    const float* vBH = v + (size_t)bh * LQ * DQ;

    int tx = t & 31, ty = t >> 5;
    int g = ty >> 2;       // key half: 0 or 1 (32 keys each)
    int sy = ty & 3;       // row group: s = sy + 4r

    float acc[10][2];
#pragma unroll
    for (int r = 0; r < 10; r++) { acc[r][0] = 0.0f; acc[r][1] = 0.0f; }
    __syncthreads();

    for (int tile = 0; tile < 8; tile++) {
        int j0 = js * 512 + tile * 64;
        __syncthreads();
        const float4* vsrc = reinterpret_cast<const float4*>(vBH + (size_t)j0 * DQ);
        float4* vdst = reinterpret_cast<float4*>(vs);
        for (int e = t; e < 64 * DQ / 4; e += 256) vdst[e] = vsrc[e];
        for (int e = t; e < NSEL * 64; e += 256) {
            int s = e >> 6, jj = e & 63;
            size_t a = (size_t)s * LQ + j0 + jj;
            float l = attnBH[a];
            float p = expf(l - sMax[s]) * sInv[s];
            attnBH[a] = p;
            ps[e] = p;
        }
        __syncthreads();
#pragma unroll 4
        for (int jl = g * 32; jl < g * 32 + 32; jl++) {
            float2 vv = *reinterpret_cast<const float2*>(&vs[jl * DQ + 2 * tx]);
#pragma unroll
            for (int r = 0; r < 10; r++) {
                float p = ps[(sy + 4 * r) * 64 + jl];
                acc[r][0] = fmaf(p, vv.x, acc[r][0]);
                acc[r][1] = fmaf(p, vv.y, acc[r][1]);
            }
        }
    }
    // merge the two key-half groups in smem (ps reused as [s][d]), then store
    __syncthreads();
    if (g == 0) {
#pragma unroll
        for (int r = 0; r < 10; r++) {
            int s = sy + 4 * r;
            ps[s * DQ + 2 * tx]     = acc[r][0];
            ps[s * DQ + 2 * tx + 1] = acc[r][1];
        }
    }
    __syncthreads();
    if (g == 1) {
#pragma unroll
        for (int r = 0; r < 10; r++) {
            int s = sy + 4 * r;
            ps[s * DQ + 2 * tx]     += acc[r][0];
            ps[s * DQ + 2 * tx + 1] += acc[r][1];
        }
    }
    __syncthreads();
    float* part = g_outSelPart + ((size_t)(bh * 4 + js)) * NSEL * DQ;
    for (int e = t; e < NSEL * DQ; e += 256) part[e] = ps[e];
}

// ============================================================================
// K5: sum the 4 P@V partials, scatter into out at the selected positions
// ============================================================================
__global__ void k_scatter(float* __restrict__ out) {   // grid BH, 256 thr
    int bh = blockIdx.x, t = threadIdx.x;
    const float* p0 = g_outSelPart + ((size_t)(bh * 4 + 0)) * NSEL * DQ;
    const float* p1 = g_outSelPart + ((size_t)(bh * 4 + 1)) * NSEL * DQ;
    const float* p2 = g_outSelPart + ((size_t)(bh * 4 + 2)) * NSEL * DQ;
    const float* p3 = g_outSelPart + ((size_t)(bh * 4 + 3)) * NSEL * DQ;
    for (int e = t; e < NSEL * DQ; e += 256) {
        int s = e >> 6, d = e & 63;
        out[((size_t)bh * LQ + g_topidx[bh * NSEL + s]) * DQ + d] =
            p0[e] + p1[e] + p2[e] + p3[e];
    }
}

// ============================================================================
extern "C" void kernel_launch(void* const* d_in, const int* in_sizes, int n_in,
                              void* d_out, int out_size) {
    const float* q = (const float*)d_in[0];
    const float* k = (const float*)d_in[1];
    const float* v = (const float*)d_in[2];
    const int* ridx = (const int*)d_in[3];

    float* out  = (float*)d_out;                        // [BH, L, D]
    float* attn = out + (size_t)BH * LQ * DQ;           // [BH, NSEL, L]

    // K1: csumA (1024 blocks, first) + measure (16384 blocks)
    k_meas_csumA<<<1024 + (BH * LQ) / 8, 256>>>(q, k, ridx, v);
    // K2: topk (64) + csumB (64)
    k_topk_csumB<<<2 * BH, 256>>>();
    // K3: csumC (1024, first) + logits (512)
    k_logits_csumC<<<1024 + BH * 8, 256>>>(q, k, v, out, attn);
    // K4: softmax probs (in place) + P@V partials
    {
        dim3 grid(BH, 4);
        k_pv<<<grid, 256>>>(v, attn);
    }
    // K5: sum partials + scatter selected rows into out
    k_scatter<<<BH, 256>>>(out);
}

// round 8
// speedup vs baseline: 1.0885x; 1.0576x over previous
#include <cuda_runtime.h>
#include <cuda_bf16.h>
#include <math.h>
#include <math_constants.h>

// Problem constants
#define BQ  8
#define HQ  8
#define BH  64          // B*H
#define LQ  2048
#define DQ  64
#define NSEL 40         // num selected queries == num sampled keys
#define SCALE 0.125f    // 64^-0.5
#define NEG_INF (-CUDART_INF_F)

// cumsum chunking: 64 chunks of 32 rows
#define NCHUNK 64
#define CHROWS 32

// k_pv key splits
#define NJS 16          // 16 splits of 128 keys each

// ---------------- scratch (device globals; no allocation allowed) ----------
__device__ float g_measure[BH * LQ];
__device__ int   g_topidx[BH * NSEL];
__device__ float g_rowMaxPart[BH * 8 * NSEL];
__device__ float g_rowSumPart[BH * 8 * NSEL];
__device__ float g_outSelPart[BH * NJS * NSEL * DQ];
__device__ float g_chunkSum[BH * NCHUNK * DQ];

// ============================================================================
// K1: fused  [csumA: 1024 blocks]  +  [measure: 16384 blocks]
// ============================================================================
__global__ __launch_bounds__(256) void k_meas_csumA(const float* __restrict__ q,
                                                    const float* __restrict__ k,
                                                    const int* __restrict__ ridx,
                                                    const float* __restrict__ v) {
    int bid = blockIdx.x;
    if (bid < 1024) {
        // ---- csumA: per-chunk sums. block = (bh, 4 chunks), thread=(sub,d)
        int bh = bid >> 4, cg = bid & 15;
        int t = threadIdx.x;
        int d = t & 63, sub = t >> 6;
        int c = cg * 4 + sub;
        const float* base = v + ((size_t)bh * LQ + c * CHROWS) * DQ;
        float s = 0.0f;
#pragma unroll 8
        for (int r = 0; r < CHROWS; r++) s += base[(size_t)r * DQ + d];
        g_chunkSum[((size_t)bh * NCHUNK + c) * DQ + d] = s;
        return;
    }
    // ---- measure: warp per query; 8 lanes per key
    const unsigned F = 0xffffffffu;
    int warp = ((bid - 1024) * 256 + (int)threadIdx.x) >> 5;
    int lane = threadIdx.x & 31;
    int bh = warp >> 11;
    int i  = warp & 2047;
    int grp = lane >> 3;          // which key of the quad
    int p   = lane & 7;           // float4 slot within 32-dim half

    const float4* qrow = reinterpret_cast<const float4*>(q + ((size_t)bh * LQ + i) * DQ);
    float4 qv0 = qrow[p];
    float4 qv1 = qrow[8 + p];
    const float4* kb4 = reinterpret_cast<const float4*>(k + (size_t)bh * LQ * DQ);
    const int* rbase = ridx + i * NSEL + grp;

    float m = NEG_INF, s = 0.0f;
#pragma unroll
    for (int h = 0; h < NSEL / 4; h += 2) {
        int ra = rbase[4 * h];
        int rb = rbase[4 * h + 4];
        const float4* kra = kb4 + (size_t)ra * (DQ / 4);
        const float4* krb = kb4 + (size_t)rb * (DQ / 4);
        float4 a0 = kra[p];
        float4 a1 = kra[8 + p];
        float4 b0 = krb[p];
        float4 b1 = krb[8 + p];
        float da = qv0.x * a0.x + qv0.y * a0.y + qv0.z * a0.z + qv0.w * a0.w;
        da += qv1.x * a1.x + qv1.y * a1.y + qv1.z * a1.z + qv1.w * a1.w;
        float db = qv0.x * b0.x + qv0.y * b0.y + qv0.z * b0.z + qv0.w * b0.w;
        db += qv1.x * b1.x + qv1.y * b1.y + qv1.z * b1.z + qv1.w * b1.w;
        da += __shfl_xor_sync(F, da, 1);
        db += __shfl_xor_sync(F, db, 1);
        da += __shfl_xor_sync(F, da, 2);
        db += __shfl_xor_sync(F, db, 2);
        da += __shfl_xor_sync(F, da, 4);
        db += __shfl_xor_sync(F, db, 4);
        m = fmaxf(m, fmaxf(da, db));
        s += da + db;
    }
    m = fmaxf(m, __shfl_xor_sync(F, m, 8));
    s += __shfl_xor_sync(F, s, 8);
    m = fmaxf(m, __shfl_xor_sync(F, m, 16));
    s += __shfl_xor_sync(F, s, 16);
    if (lane == 0) g_measure[bh * LQ + i] = m - s * (1.0f / (float)LQ);
}

// ============================================================================
// K2: fused  [topk: 64 blocks]  +  [csumB: 64 blocks]
// ============================================================================
__global__ __launch_bounds__(256) void k_topk_csumB() {
    int bid = blockIdx.x;
    if (bid >= BH) {
        // ---- csumB
        int bh = bid - BH;
        int d = threadIdx.x;
        if (d < DQ) {
            float run = 0.0f;
#pragma unroll
            for (int c = 0; c < NCHUNK; c++) {
                size_t a = ((size_t)bh * NCHUNK + c) * DQ + d;
                float x = g_chunkSum[a];
                g_chunkSum[a] = run;   // exclusive
                run += x;
            }
        }
        return;
    }
    // ---- topk: radix select + rank sort
    __shared__ unsigned ukey[LQ];
    __shared__ int hist[256];
    __shared__ int ssum[256];
    __shared__ int wsum[8];
    __shared__ int s_chosen;
    __shared__ int s_target;
    __shared__ int cnt_gt;
    __shared__ unsigned selKey[64];
    __shared__ int selIdx[64];
    __shared__ int tcnt[256];

    int bh = bid, t = threadIdx.x, lane = t & 31, w = t >> 5;

    for (int e = t; e < LQ; e += 256) {
        unsigned b = __float_as_uint(g_measure[bh * LQ + e]);
        ukey[e] = (b & 0x80000000u) ? ~b : (b | 0x80000000u);
    }
    if (t == 0) { s_target = NSEL; cnt_gt = 0; }
    __syncthreads();

    unsigned prefix = 0;
    for (int pass = 3; pass >= 0; pass--) {
        int shift = pass * 8;
        hist[t] = 0;
        __syncthreads();
        unsigned himask = (pass == 3) ? 0u : (0xFFFFFFFFu << (shift + 8));
        for (int e = t; e < LQ; e += 256) {
            unsigned u = ukey[e];
            if ((u & himask) == (prefix & himask))
                atomicAdd(&hist[(u >> shift) & 255], 1);
        }
        __syncthreads();
        int r = 255 - t;
        int x = hist[r];
#pragma unroll
        for (int o = 1; o < 32; o <<= 1) {
            int y = __shfl_up_sync(0xffffffffu, x, o);
            if (lane >= o) x += y;
        }
        if (lane == 31) wsum[w] = x;
        __syncthreads();
        if (w == 0 && lane < 8) {
            int y = wsum[lane];
#pragma unroll
            for (int o = 1; o < 8; o <<= 1) {
                int z = __shfl_up_sync(0xffu, y, o);
                if (lane >= o) y += z;
            }
            wsum[lane] = y;
        }
        __syncthreads();
        int S = x + (w > 0 ? wsum[w - 1] : 0);
        ssum[r] = S;
        __syncthreads();
        int target = s_target;
        int Sb = ssum[t];
        int Sb1 = (t == 255) ? 0 : ssum[t + 1];
        if (Sb >= target && Sb1 < target) s_chosen = t;
        __syncthreads();
        int chosen = s_chosen;
        prefix |= ((unsigned)chosen) << shift;
        if (t == 0) s_target = target - ((chosen == 255) ? 0 : ssum[chosen + 1]);
        __syncthreads();
    }
    unsigned T = prefix;
    int need_eq = s_target;
    int count_gt = NSEL - need_eq;

    int mytie = 0;
#pragma unroll
    for (int e2 = 0; e2 < 8; e2++) {
        int e = t * 8 + e2;
        unsigned u = ukey[e];
        if (u > T) {
            int p = atomicAdd(&cnt_gt, 1);
            selKey[p] = u; selIdx[p] = e;
        } else if (u == T) mytie++;
    }
    tcnt[t] = mytie;
    __syncthreads();
    {
        int x = tcnt[t];
#pragma unroll
        for (int o = 1; o < 32; o <<= 1) {
            int y = __shfl_up_sync(0xffffffffu, x, o);
            if (lane >= o) x += y;
        }
        if (lane == 31) wsum[w] = x;
        __syncthreads();
        if (w == 0 && lane < 8) {
            int y = wsum[lane];
#pragma unroll
            for (int o = 1; o < 8; o <<= 1) {
                int z = __shfl_up_sync(0xffu, y, o);
                if (lane >= o) y += z;
            }
            wsum[lane] = y;
        }
        __syncthreads();
        int run = x - tcnt[t] + (w > 0 ? wsum[w - 1] : 0);
#pragma unroll
        for (int e2 = 0; e2 < 8; e2++) {
            int e = t * 8 + e2;
            if (ukey[e] == T) {
                if (run < need_eq) { selKey[count_gt + run] = T; selIdx[count_gt + run] = e; }
                run++;
            }
        }
    }
    __syncthreads();
    if (t < NSEL) {
        unsigned mk = selKey[t]; int mi = selIdx[t];
        int rank = 0;
        for (int f = 0; f < NSEL; f++) {
            unsigned fk = selKey[f]; int fi = selIdx[f];
            if (fk > mk || (fk == mk && fi < mi)) rank++;
        }
        g_topidx[bh * NSEL + rank] = mi;
    }
}

// ============================================================================
// K3: fused  [csumC: 1024 blocks]  +  [logits: 512 blocks]
// ============================================================================
__global__ __launch_bounds__(256) void k_logits_csumC(const float* __restrict__ q,
                                                      const float* __restrict__ k,
                                                      const float* __restrict__ v,
                                                      float* __restrict__ out,
                                                      float* __restrict__ attn) {
    __shared__ float qs[NSEL * DQ];        // 40x64
    __shared__ float ks[128 * 65];         // padded
    __shared__ int   sidx[NSEL];

    int bid = blockIdx.x;
    if (bid < 1024) {
        // ---- csumC
        int bh = bid >> 4, cg = bid & 15;
        int t = threadIdx.x;
        int d = t & 63, sub = t >> 6;
        int c = cg * 4 + sub;
        const float* base = v + ((size_t)bh * LQ + c * CHROWS) * DQ;
        float* obase = out + ((size_t)bh * LQ + c * CHROWS) * DQ;
        float run = g_chunkSum[((size_t)bh * NCHUNK + c) * DQ + d];
#pragma unroll 8
        for (int r = 0; r < CHROWS; r++) {
            run += base[(size_t)r * DQ + d];
            obase[(size_t)r * DQ + d] = run;
        }
        return;
    }
    // ---- logits
    int lb = bid - 1024;
    int bh = lb >> 3, js = lb & 7, t = threadIdx.x;
    if (t < NSEL) sidx[t] = g_topidx[bh * NSEL + t];
    __syncthreads();

    for (int e = t; e < NSEL * DQ; e += 256) {
        int s = e >> 6, d = e & 63;
        qs[e] = q[((size_t)bh * LQ + sidx[s]) * DQ + d];
    }

    float* attnBH = attn + (size_t)bh * NSEL * LQ;
    int tx = t & 63, ty = t >> 6;

    for (int sub = 0; sub < 2; sub++) {
        int j0 = js * 256 + sub * 128;
        __syncthreads();
        for (int e = t; e < 128 * DQ; e += 256) {
            int r = e >> 6, d = e & 63;
            ks[r * 65 + d] = k[((size_t)bh * LQ + j0 + r) * DQ + d];
        }
        __syncthreads();

        float acc[10][2];
#pragma unroll
        for (int r = 0; r < 10; r++) { acc[r][0] = 0.0f; acc[r][1] = 0.0f; }

#pragma unroll 4
        for (int d = 0; d < DQ; d++) {
            float k0 = ks[tx * 65 + d];
            float k1 = ks[(tx + 64) * 65 + d];
#pragma unroll
            for (int r = 0; r < 10; r++) {
                float qv = qs[(ty + 4 * r) * DQ + d];
                acc[r][0] = fmaf(qv, k0, acc[r][0]);
                acc[r][1] = fmaf(qv, k1, acc[r][1]);
            }
        }
#pragma unroll
        for (int r = 0; r < 10; r++) {
            int s = ty + 4 * r;
            int lim = sidx[s];
            int jg0 = j0 + tx;
            int jg1 = j0 + tx + 64;
            attnBH[(size_t)s * LQ + jg0] = (jg0 > lim) ? NEG_INF : acc[r][0] * SCALE;
            attnBH[(size_t)s * LQ + jg1] = (jg1 > lim) ? NEG_INF : acc[r][1] * SCALE;
        }
    }
    __syncthreads();

    // partial softmax stats over this block's 256-key span
    int w = t >> 5, lane = t & 31;
    for (int rr = 0; rr < 5; rr++) {
        int s = w + 8 * rr;
        size_t base = (size_t)s * LQ + js * 256;
        float m = NEG_INF;
#pragma unroll
        for (int u = 0; u < 8; u++) m = fmaxf(m, attnBH[base + lane + 32 * u]);
        m = fmaxf(m, __shfl_xor_sync(0xffffffffu, m, 16));
        m = fmaxf(m, __shfl_xor_sync(0xffffffffu, m, 8));
        m = fmaxf(m, __shfl_xor_sync(0xffffffffu, m, 4));
        m = fmaxf(m, __shfl_xor_sync(0xffffffffu, m, 2));
        m = fmaxf(m, __shfl_xor_sync(0xffffffffu, m, 1));
        float ssum = 0.0f;
        if (m > NEG_INF) {
#pragma unroll
            for (int u = 0; u < 8; u++) ssum += expf(attnBH[base + lane + 32 * u] - m);
        }
        ssum += __shfl_xor_sync(0xffffffffu, ssum, 16);
        ssum += __shfl_xor_sync(0xffffffffu, ssum, 8);
        ssum += __shfl_xor_sync(0xffffffffu, ssum, 4);
        ssum += __shfl_xor_sync(0xffffffffu, ssum, 2);
        ssum += __shfl_xor_sync(0xffffffffu, ssum, 1);
        if (lane == 0) {
            g_rowMaxPart[(bh * 8 + js) * NSEL + s] = m;
            g_rowSumPart[(bh * 8 + js) * NSEL + s] = ssum;
        }
    }
}

// ============================================================================
// K4: rowMax/rowInv from partials in-block; probs -> attn in place;
// P@V partial per (bh, js) written WITHOUT atomics to g_outSelPart.
// grid (BH, NJS=16 splits of 128 keys), block 256, 2 inner tiles of 64 keys.
// 1024 blocks -> ~4 CTAs/SM (was 256 blocks, grid-limited at occ 21%).
// ============================================================================
__global__ void k_pv(const float* __restrict__ v, float* __restrict__ attn) {
    __shared__ float vs[64 * DQ];     // 16 KB
    __shared__ float ps[NSEL * 64];   // 10 KB (reused at end as [s][d] merge)
    __shared__ float sMax[NSEL], sInv[NSEL];

    int bh = blockIdx.x, js = blockIdx.y, t = threadIdx.x;
    if (t < NSEL) {
        float fm = NEG_INF;
#pragma unroll
        for (int p = 0; p < 8; p++)
            fm = fmaxf(fm, g_rowMaxPart[(bh * 8 + p) * NSEL + t]);
        float fs = 0.0f;
#pragma unroll
        for (int p = 0; p < 8; p++) {
            float pm = g_rowMaxPart[(bh * 8 + p) * NSEL + t];
            float pssum = g_rowSumPart[(bh * 8 + p) * NSEL + t];
            fs += pssum * expf(pm - fm);
        }
        sMax[t] = fm;
        sInv[t] = 1.0f / fs;
    }

    float* attnBH = attn + (size_t)bh * NSEL * LQ;
    const float* vBH = v + (size_t)bh * LQ * DQ;

    int tx = t & 31, ty = t >> 5;
    int g = ty >> 2;       // key half: 0 or 1 (32 keys each)
    int sy = ty & 3;       // row group: s = sy + 4r

    float acc[10][2];
#pragma unroll
    for (int r = 0; r < 10; r++) { acc[r][0] = 0.0f; acc[r][1] = 0.0f; }
    __syncthreads();

#pragma unroll
    for (int tile = 0; tile < 2; tile++) {
        int j0 = js * 128 + tile * 64;
        __syncthreads();
        const float4* vsrc = reinterpret_cast<const float4*>(vBH + (size_t)j0 * DQ);
        float4* vdst = reinterpret_cast<float4*>(vs);
        for (int e = t; e < 64 * DQ / 4; e += 256) vdst[e] = vsrc[e];
        for (int e = t; e < NSEL * 64; e += 256) {
            int s = e >> 6, jj = e & 63;
            size_t a = (size_t)s * LQ + j0 + jj;
            float l = attnBH[a];
            float p = expf(l - sMax[s]) * sInv[s];
            attnBH[a] = p;
            ps[e] = p;
        }
        __syncthreads();
#pragma unroll 4
        for (int jl = g * 32; jl < g * 32 + 32; jl++) {
            float2 vv = *reinterpret_cast<const float2*>(&vs[jl * DQ + 2 * tx]);
#pragma unroll
            for (int r = 0; r < 10; r++) {
                float p = ps[(sy + 4 * r) * 64 + jl];
                acc[r][0] = fmaf(p, vv.x, acc[r][0]);
                acc[r][1] = fmaf(p, vv.y, acc[r][1]);
            }
        }
    }
    // merge the two key-half groups in smem (ps reused as [s][d]), then store
    __syncthreads();
    if (g == 0) {
#pragma unroll
        for (int r = 0; r < 10; r++) {
            int s = sy + 4 * r;
            ps[s * DQ + 2 * tx]     = acc[r][0];
            ps[s * DQ + 2 * tx + 1] = acc[r][1];
        }
    }
    __syncthreads();
    if (g == 1) {
#pragma unroll
        for (int r = 0; r < 10; r++) {
            int s = sy + 4 * r;
            ps[s * DQ + 2 * tx]     += acc[r][0];
            ps[s * DQ + 2 * tx + 1] += acc[r][1];
        }
    }
    __syncthreads();
    float* part = g_outSelPart + ((size_t)(bh * NJS + js)) * NSEL * DQ;
    for (int e = t; e < NSEL * DQ; e += 256) part[e] = ps[e];
}

// ============================================================================
// K5: sum the NJS P@V partials, scatter into out at the selected positions
// ============================================================================
__global__ void k_scatter(float* __restrict__ out) {   // grid BH, 256 thr
    int bh = blockIdx.x, t = threadIdx.x;
    const float* base = g_outSelPart + (size_t)bh * NJS * NSEL * DQ;
    for (int e = t; e < NSEL * DQ; e += 256) {
        int s = e >> 6, d = e & 63;
        float acc = 0.0f;
#pragma unroll
        for (int p = 0; p < NJS; p++) acc += base[(size_t)p * NSEL * DQ + e];
        out[((size_t)bh * LQ + g_topidx[bh * NSEL + s]) * DQ + d] = acc;
    }
}

// ============================================================================
extern "C" void kernel_launch(void* const* d_in, const int* in_sizes, int n_in,
                              void* d_out, int out_size) {
    const float* q = (const float*)d_in[0];
    const float* k = (const float*)d_in[1];
    const float* v = (const float*)d_in[2];
    const int* ridx = (const int*)d_in[3];

    float* out  = (float*)d_out;                        // [BH, L, D]
    float* attn = out + (size_t)BH * LQ * DQ;           // [BH, NSEL, L]

    // K1: csumA (1024 blocks, first) + measure (16384 blocks)
    k_meas_csumA<<<1024 + (BH * LQ) / 8, 256>>>(q, k, ridx, v);
    // K2: topk (64) + csumB (64)
    k_topk_csumB<<<2 * BH, 256>>>();
    // K3: csumC (1024, first) + logits (512)
    k_logits_csumC<<<1024 + BH * 8, 256>>>(q, k, v, out, attn);
    // K4: softmax probs (in place) + P@V partials (grid 64x16)
    {
        dim3 grid(BH, NJS);
        k_pv<<<grid, 256>>>(v, attn);
    }
    // K5: sum partials + scatter selected rows into out
    k_scatter<<<BH, 256>>>(out);
}